// round 8
// baseline (speedup 1.0000x reference)
#include <cuda_runtime.h>
#include <cuda_fp16.h>
#include <stdint.h>

#define BB 8
#define NN 4096
#define NEG_SLOPE 0.01f

// GEMM: M=512 ((b,f) rows), N=4096 (i), K=4096 (j), fp16 single pass.
// CTA tile 128x128, K chunk 64, K-split 2. B converted from raw adj in-kernel.
#define STAGE_BYTES 49152          // A fp16 16KB + Braw int32 32KB
#define BHALF_OFF   98304          // fp16 B buffer, 16KB (64j x 256B swizzled)
#define SMEM_DYN    114688         // 112KB -> 2 CTAs/SM

// -------- scratch (device globals; no allocation allowed) --------
__device__ __half g_hT[(size_t)BB * 64 * NN];      // hT[b][f][n], row (b*64+f)
__device__ float g_s1[BB * NN];
__device__ float g_s2p[2][BB * NN];                // per-K-slice partials
__device__ float g_hsumP[16][BB][64];              // per-block partials
__device__ __align__(16) float g_hsum[BB * 64];

// -------- helpers --------
__device__ __forceinline__ uint32_t smem_u32(const void* p) {
    uint32_t a;
    asm("{ .reg .u64 t; cvta.to.shared.u64 t, %1; cvt.u32.u64 %0, t; }" : "=r"(a) : "l"(p));
    return a;
}
#define SW128(x) ((x) ^ (((x) >> 3) & 0x70))
#define SW2(x)   ((x) ^ (((x) >> 5) & 0x70))
__device__ __forceinline__ void cp16(uint32_t s, const void* g) {
    asm volatile("cp.async.cg.shared.global [%0], [%1], 16;" :: "r"(s), "l"(g) : "memory");
}
__device__ __forceinline__ void cp16z(uint32_t s, const void* g, uint32_t sz) {
    asm volatile("cp.async.cg.shared.global [%0], [%1], 16, %2;" :: "r"(s), "l"(g), "r"(sz) : "memory");
}
#define CP_COMMIT() asm volatile("cp.async.commit_group;" ::: "memory")

__device__ __forceinline__ void mma_f16(float* c, const uint32_t* A, const uint32_t* B) {
    asm volatile(
        "mma.sync.aligned.m16n8k16.row.col.f32.f16.f16.f32 "
        "{%0,%1,%2,%3}, {%4,%5,%6,%7}, {%8,%9}, {%0,%1,%2,%3};"
        : "+f"(c[0]), "+f"(c[1]), "+f"(c[2]), "+f"(c[3])
        : "r"(A[0]), "r"(A[1]), "r"(A[2]), "r"(A[3]), "r"(B[0]), "r"(B[1]));
}
#define LDSM4(r0, r1, r2, r3, addr) \
    asm volatile("ldmatrix.sync.aligned.m8n8.x4.shared.b16 {%0,%1,%2,%3}, [%4];" \
                 : "=r"(r0), "=r"(r1), "=r"(r2), "=r"(r3) : "r"(addr))
#define LDSM4T(r0, r1, r2, r3, addr) \
    asm volatile("ldmatrix.sync.aligned.m8n8.x4.trans.shared.b16 {%0,%1,%2,%3}, [%4];" \
                 : "=r"(r0), "=r"(r1), "=r"(r2), "=r"(r3) : "r"(addr))

// -------- kernel 2: h = inp@W^T + b (row 0 zeroed); fp16 h + s1 + hsum partials --------
__global__ void __launch_bounds__(256) k_compute_h(const float* __restrict__ inp,
                                                   const float* __restrict__ W_w,
                                                   const float* __restrict__ W_b,
                                                   const float* __restrict__ a) {
    __shared__ __align__(16) float Wsh[64 * 64];
    __shared__ float bsh[64];
    __shared__ float wred[8][64];
    int tid = threadIdx.x, lane = tid & 31, wid = tid >> 5, b = blockIdx.y;
    int n = blockIdx.x * 256 + tid;
    for (int i = tid; i < 64 * 64; i += 256) Wsh[i] = W_w[i];
    if (tid < 64) bsh[tid] = W_b[tid];
    __syncthreads();

    float x[64];
    const float4* src = reinterpret_cast<const float4*>(inp + ((size_t)b * NN + n) * 64);
#pragma unroll
    for (int q = 0; q < 16; q++) {
        float4 v = src[q];
        x[4 * q] = v.x; x[4 * q + 1] = v.y; x[4 * q + 2] = v.z; x[4 * q + 3] = v.w;
    }
    float s1 = 0.f;
    for (int f = 0; f < 64; f++) {
        const float4* wr = reinterpret_cast<const float4*>(Wsh + f * 64);
        float t0 = bsh[f], t1 = 0.f, t2 = 0.f, t3 = 0.f;
#pragma unroll
        for (int q = 0; q < 16; q += 4) {
            float4 w0 = wr[q], w1 = wr[q + 1], w2 = wr[q + 2], w3 = wr[q + 3];
            t0 = fmaf(x[4*q+0],  w0.x, t0); t0 = fmaf(x[4*q+1],  w0.y, t0);
            t0 = fmaf(x[4*q+2],  w0.z, t0); t0 = fmaf(x[4*q+3],  w0.w, t0);
            t1 = fmaf(x[4*q+4],  w1.x, t1); t1 = fmaf(x[4*q+5],  w1.y, t1);
            t1 = fmaf(x[4*q+6],  w1.z, t1); t1 = fmaf(x[4*q+7],  w1.w, t1);
            t2 = fmaf(x[4*q+8],  w2.x, t2); t2 = fmaf(x[4*q+9],  w2.y, t2);
            t2 = fmaf(x[4*q+10], w2.z, t2); t2 = fmaf(x[4*q+11], w2.w, t2);
            t3 = fmaf(x[4*q+12], w3.x, t3); t3 = fmaf(x[4*q+13], w3.y, t3);
            t3 = fmaf(x[4*q+14], w3.z, t3); t3 = fmaf(x[4*q+15], w3.w, t3);
        }
        float acc = (t0 + t1) + (t2 + t3);
        if (n == 0) acc = 0.f;
        g_hT[((size_t)b * 64 + f) * NN + n] = __float2half(acc);
        s1 = fmaf(acc, a[(size_t)f * NN + n], s1);
        float v = acc;
#pragma unroll
        for (int off = 16; off > 0; off >>= 1)
            v += __shfl_xor_sync(0xFFFFFFFFu, v, off);
        if (lane == 0) wred[wid][f] = v;
    }
    g_s1[b * NN + n] = s1;
    __syncthreads();
    if (tid < 64) {
        float t = 0.f;
#pragma unroll
        for (int w = 0; w < 8; w++) t += wred[w][tid];
        g_hsumP[blockIdx.x][b][tid] = t;
    }
}

// -------- kernel 2b: finish hsum --------
__global__ void k_hsum_final() {
    int b = threadIdx.x >> 6, f = threadIdx.x & 63;   // 512 threads
    float t = 0.f;
#pragma unroll
    for (int p = 0; p < 16; p++) t += g_hsumP[p][b][f];
    g_hsum[b * 64 + f] = t;
}

// -------- kernel 4: big GEMM, B = adj converted in-kernel --------
__device__ __forceinline__ void load_chunk(uint32_t stage, const char* Ah,
                                           const int* __restrict__ adj,
                                           int i0, int cglob, int tid) {
    // A: 128 rows x 128B, SW128
    size_t koffA = (size_t)cglob * 128;
#pragma unroll
    for (int p = 0; p < 4; p++) {
        int q = tid + p * 256;
        int row = q >> 3, cb = (q & 7) * 16;
        cp16(stage + SW128((uint32_t)(row * 128 + cb)),
             Ah + (size_t)row * 8192 + koffA + cb);
    }
    // Braw: 64 j-rows x 512B int32, SW2 swizzle, zero-fill OOB row (valid src addr)
    int jbase = cglob * 64;
#pragma unroll
    for (int p = 0; p < 8; p++) {
        int q = tid + p * 256;
        int row = q >> 5, cb = (q & 31) * 16;
        int jg = jbase + row;
        bool ok = (jg + 1 < NN);
        uint32_t dst = stage + 16384u + SW2((uint32_t)(row * 512 + cb));
        const char* src = ok ? (const char*)(adj + (size_t)(jg + 1) * NN + i0) + cb
                             : (const char*)adj;   // valid dummy, sz=0 zero-fills
        cp16z(dst, src, ok ? 16u : 0u);
    }
}

__global__ void __launch_bounds__(256, 2) k_gemm(const float* __restrict__ a,
                                                 const int* __restrict__ adj) {
    extern __shared__ char smem[];
    uint32_t sb = smem_u32(smem);
    int tid = threadIdx.x, lane = tid & 31, wid = tid >> 5;
    int wm = wid & 3, wn = wid >> 2;          // warp tile: rows wm*32, cols wn*64
    int mtile = blockIdx.x, i0 = blockIdx.y * 128;
    int kslice = blockIdx.z, c0 = kslice * 32;  // 32 chunks of 64 per slice

    const char* Ah = (const char*)g_hT + (size_t)mtile * 128 * 8192;

    float acc[2][8][4];
#pragma unroll
    for (int mt = 0; mt < 2; mt++)
#pragma unroll
        for (int nt = 0; nt < 8; nt++)
#pragma unroll
            for (int r = 0; r < 4; r++) acc[mt][nt][r] = 0.f;

    // A LDSM addressing (SW128)
    uint32_t cx = (uint32_t)((lane & 7) << 4);
    uint32_t aoff = (uint32_t)(wm * 32 + (lane & 15)) * 128u;
    uint32_t khA = (uint32_t)(((lane >> 4) & 1) << 4);
    // B LDSM.trans addressing into Bhalf [j][i]: addr = (j*256 + colbytes) ^ ((j&15)<<4)
    uint32_t bj = (uint32_t)(lane & 15);
    uint32_t bcx = bj << 4;
    uint32_t bbase = bj * 256u + (uint32_t)(wn * 64 + ((lane >> 4) << 3)) * 2u;
    // convert-phase mapping
    int cj = tid >> 2, ciq = tid & 3;
    uint32_t cswz = (uint32_t)((cj & 15) << 4);

    // prologue: chunks 0,1
    load_chunk(sb, Ah, adj, i0, c0, tid);
    CP_COMMIT();
    load_chunk(sb + STAGE_BYTES, Ah, adj, i0, c0 + 1, tid);
    CP_COMMIT();

    for (int c = 0; c < 32; c++) {
        asm volatile("cp.async.wait_group 1;" ::: "memory");
        __syncthreads();   // chunk c arrived; Bhalf free (prev chunk's LDSMs done)
        uint32_t so = sb + (uint32_t)(c & 1) * STAGE_BYTES;
        // convert Braw(int32 [j][i]) -> Bhalf(fp16 [j][i], swizzled)
        {
            const char* brp = smem + (size_t)(c & 1) * STAGE_BYTES + 16384;
            char* bhp = smem + BHALF_OFF + cj * 256;
#pragma unroll
            for (int p = 0; p < 8; p++) {
                uint32_t roff = (uint32_t)(cj * 512 + ciq * 128 + p * 16);
                int4 v = *reinterpret_cast<const int4*>(brp + SW2(roff));
                uint32_t lo = (v.x > 0 ? 0x3C00u : 0u) | (v.y > 0 ? 0x3C000000u : 0u);
                uint32_t hi = (v.z > 0 ? 0x3C00u : 0u) | (v.w > 0 ? 0x3C000000u : 0u);
                uint32_t dcol = (uint32_t)((ciq * 32 + p * 4) * 2);
                *reinterpret_cast<uint2*>(bhp + (dcol ^ cswz)) = make_uint2(lo, hi);
            }
        }
        __syncthreads();   // Bhalf ready
#pragma unroll
        for (int ks = 0; ks < 4; ks++) {
            uint32_t kA = ((uint32_t)(ks * 32) + khA) ^ cx;
            uint32_t bfr[8][2];
#pragma unroll
            for (int ntp = 0; ntp < 4; ntp++) {
                uint32_t boffs = (bbase + (uint32_t)(ntp * 32)) ^ bcx;
                LDSM4T(bfr[2 * ntp][0], bfr[2 * ntp][1], bfr[2 * ntp + 1][0], bfr[2 * ntp + 1][1],
                       sb + BHALF_OFF + (uint32_t)(ks * 4096) + boffs);
            }
            uint32_t ah[2][4];
#pragma unroll
            for (int mt = 0; mt < 2; mt++)
                LDSM4(ah[mt][0], ah[mt][1], ah[mt][2], ah[mt][3],
                      so + aoff + (uint32_t)mt * 2048 + kA);
#pragma unroll
            for (int mt = 0; mt < 2; mt++)
#pragma unroll
                for (int nt = 0; nt < 8; nt++)
                    mma_f16(acc[mt][nt], ah[mt], bfr[nt]);
        }
        __syncthreads();   // all warps done reading stage c&1
        if (c + 2 < 32)
            load_chunk(sb + (uint32_t)(c & 1) * STAGE_BYTES, Ah, adj, i0, c0 + c + 2, tid);
        CP_COMMIT();
    }

    // epilogue: s2p[kslice][b][i] = sum_f C[(b,f)][i] * a2[f][i]
    int tig = lane & 3, grp = lane >> 2;
    float* a2s = (float*)smem;                        // [64][129]
    float* part = (float*)(smem + 64 * 129 * 4);      // [8 warps][64]
    for (int idx = tid; idx < 64 * 128; idx += 256) {
        int f = idx >> 7, cc = idx & 127;
        a2s[f * 129 + cc] = a[(size_t)(64 + f) * NN + i0 + cc];
    }
    __syncthreads();

    float p[8][2];
#pragma unroll
    for (int nt = 0; nt < 8; nt++) { p[nt][0] = 0.f; p[nt][1] = 0.f; }
#pragma unroll
    for (int mt = 0; mt < 2; mt++) {
        int f0 = (wm * 32 + mt * 16 + grp) & 63;
        int f1 = (wm * 32 + mt * 16 + grp + 8) & 63;
#pragma unroll
        for (int nt = 0; nt < 8; nt++) {
            int col = wn * 64 + nt * 8 + tig * 2;
            p[nt][0] += acc[mt][nt][0] * a2s[f0 * 129 + col] +
                        acc[mt][nt][2] * a2s[f1 * 129 + col];
            p[nt][1] += acc[mt][nt][1] * a2s[f0 * 129 + col + 1] +
                        acc[mt][nt][3] * a2s[f1 * 129 + col + 1];
        }
    }
#pragma unroll
    for (int off = 16; off >= 4; off >>= 1)
#pragma unroll
        for (int nt = 0; nt < 8; nt++) {
            p[nt][0] += __shfl_xor_sync(0xFFFFFFFFu, p[nt][0], off);
            p[nt][1] += __shfl_xor_sync(0xFFFFFFFFu, p[nt][1], off);
        }
    if (lane < 4) {
#pragma unroll
        for (int nt = 0; nt < 8; nt++) {
            part[wid * 64 + nt * 8 + tig * 2]     = p[nt][0];
            part[wid * 64 + nt * 8 + tig * 2 + 1] = p[nt][1];
        }
    }
    __syncthreads();
    {
        int bloc = tid >> 7, col = tid & 127;
        int wnn = col >> 6, c64 = col & 63;
        int w0 = wnn * 4 + bloc * 2;   // warps covering this (batch, col-block)
        float v = part[w0 * 64 + c64] + part[(w0 + 1) * 64 + c64];
        g_s2p[kslice][(size_t)(mtile * 2 + bloc) * NN + i0 + col] = v;
    }
}

// -------- kernel 5: out[b,n,f] = leaky(s[b,n] * hsum[b,f]) --------
__global__ void __launch_bounds__(256) k_out(float* __restrict__ out) {
    __shared__ __align__(16) float hs[64];
    int b = blockIdx.y, n0 = blockIdx.x * 16, tid = threadIdx.x;
    if (tid < 64) hs[tid] = g_hsum[b * 64 + tid];
    __syncthreads();
    int r = tid >> 4, q = tid & 15;
    int n = n0 + r;
    float s = (n == 0) ? 0.f
                       : (g_s1[b * NN + n] + g_s2p[0][b * NN + n] + g_s2p[1][b * NN + n]);
    float4 h4 = reinterpret_cast<const float4*>(hs)[q];
    float4 v;
    v.x = s * h4.x; v.y = s * h4.y; v.z = s * h4.z; v.w = s * h4.w;
    v.x = v.x >= 0.f ? v.x : NEG_SLOPE * v.x;
    v.y = v.y >= 0.f ? v.y : NEG_SLOPE * v.y;
    v.z = v.z >= 0.f ? v.z : NEG_SLOPE * v.z;
    v.w = v.w >= 0.f ? v.w : NEG_SLOPE * v.w;
    reinterpret_cast<float4*>(out + ((size_t)b * NN + n) * 64)[q] = v;
}

extern "C" void kernel_launch(void* const* d_in, const int* in_sizes, int n_in,
                              void* d_out, int out_size) {
    const float* inp = (const float*)d_in[0];
    const int*   adj = (const int*)d_in[1];
    const float* W_w = (const float*)d_in[2];
    const float* W_b = (const float*)d_in[3];
    const float* a   = (const float*)d_in[4];
    float* out = (float*)d_out;
    cudaFuncSetAttribute(k_gemm, cudaFuncAttributeMaxDynamicSharedMemorySize, SMEM_DYN);
    k_compute_h<<<dim3(16, 8), 256>>>(inp, W_w, W_b, a);
    k_hsum_final<<<1, 512>>>();
    k_gemm<<<dim3(4, 32, 2), 256, SMEM_DYN>>>(a, adj);
    k_out<<<dim3(256, 8), 256>>>(out);
}

// round 9
// speedup vs baseline: 1.2251x; 1.2251x over previous
#include <cuda_runtime.h>
#include <cuda_fp16.h>
#include <stdint.h>

#define BB 8
#define NN 4096
#define NEG_SLOPE 0.01f
#define KSPLIT 4

// GEMM: M=512 ((b,f) rows), N=4096 (i), K=4096 (j), fp16 single pass.
// CTA tile 128x128, K chunk 64, K-split 4 (each CTA does K=1024).
#define STAGE_BYTES 32768          // A 16KB + B 16KB
#define NSTAGE 3
#define SMEM_DYN (NSTAGE * STAGE_BYTES)   // 96KB -> 2 CTAs/SM

// -------- scratch (device globals; no allocation allowed) --------
__device__ __half g_maskT[(size_t)NN * NN];        // maskT[i][j]
__device__ __half g_hT[(size_t)BB * 64 * NN];      // hT[b][f][n], row (b*64+f)
__device__ float g_s1[BB * NN];
__device__ float g_s2p[KSPLIT][BB * NN];           // per-K-slice partials
__device__ float g_hsumP[16][BB][64];              // per-block partials
__device__ __align__(16) float g_hsum[BB * 64];

// -------- helpers --------
__device__ __forceinline__ uint32_t smem_u32(const void* p) {
    uint32_t a;
    asm("{ .reg .u64 t; cvta.to.shared.u64 t, %1; cvt.u32.u64 %0, t; }" : "=r"(a) : "l"(p));
    return a;
}
#define SW128(x) ((x) ^ (((x) >> 3) & 0x70))
__device__ __forceinline__ void cp16(uint32_t s, const void* g) {
    asm volatile("cp.async.cg.shared.global [%0], [%1], 16;" :: "r"(s), "l"(g) : "memory");
}
#define CP_COMMIT() asm volatile("cp.async.commit_group;" ::: "memory")

__device__ __forceinline__ void mma_f16(float* c, const uint32_t* A, const uint32_t* B) {
    asm volatile(
        "mma.sync.aligned.m16n8k16.row.col.f32.f16.f16.f32 "
        "{%0,%1,%2,%3}, {%4,%5,%6,%7}, {%8,%9}, {%0,%1,%2,%3};"
        : "+f"(c[0]), "+f"(c[1]), "+f"(c[2]), "+f"(c[3])
        : "r"(A[0]), "r"(A[1]), "r"(A[2]), "r"(A[3]), "r"(B[0]), "r"(B[1]));
}
#define LDSM4(r0, r1, r2, r3, addr) \
    asm volatile("ldmatrix.sync.aligned.m8n8.x4.shared.b16 {%0,%1,%2,%3}, [%4];" \
                 : "=r"(r0), "=r"(r1), "=r"(r2), "=r"(r3) : "r"(addr))

// -------- kernel 1 (fused): blocks 0-127 compute_h, blocks 128-4223 transpose --------
__global__ void __launch_bounds__(256) k_prep(const float* __restrict__ inp,
                                              const float* __restrict__ W_w,
                                              const float* __restrict__ W_b,
                                              const float* __restrict__ a,
                                              const int* __restrict__ adj) {
    __shared__ __align__(16) float Wsh[64 * 64];
    __shared__ float bsh[64];
    __shared__ float wred[8][64];
    __shared__ __half tile[64][72];
    int tid = threadIdx.x;
    int bidx = blockIdx.x;

    if (bidx >= 128) {
        // ---------------- transpose: maskT[i][j] = (adj[j+1][i] > 0), j==N-1 -> 0
        int t = bidx - 128;
        int i0 = (t >> 6) * 64, j0 = (t & 63) * 64;
        int jl = tid >> 4;            // 0..15
        int il4 = (tid & 15) * 4;     // 0..60
#pragma unroll
        for (int pass = 0; pass < 4; pass++) {
            int j = j0 + jl + pass * 16;
            if (j + 1 < NN) {
                int4 v = *reinterpret_cast<const int4*>(adj + (size_t)(j + 1) * NN + i0 + il4);
                tile[il4 + 0][jl + pass * 16] = __float2half(v.x > 0 ? 1.f : 0.f);
                tile[il4 + 1][jl + pass * 16] = __float2half(v.y > 0 ? 1.f : 0.f);
                tile[il4 + 2][jl + pass * 16] = __float2half(v.z > 0 ? 1.f : 0.f);
                tile[il4 + 3][jl + pass * 16] = __float2half(v.w > 0 ? 1.f : 0.f);
            } else {
                tile[il4 + 0][jl + pass * 16] = __float2half(0.f);
                tile[il4 + 1][jl + pass * 16] = __float2half(0.f);
                tile[il4 + 2][jl + pass * 16] = __float2half(0.f);
                tile[il4 + 3][jl + pass * 16] = __float2half(0.f);
            }
        }
        __syncthreads();
        int il = tid >> 3;            // 0..31
        int jc = (tid & 7) * 8;       // 0..56
#pragma unroll
        for (int pass = 0; pass < 2; pass++) {
            int row = il + pass * 32;
            uint4 v = *reinterpret_cast<const uint4*>(&tile[row][jc]);
            *reinterpret_cast<uint4*>(&g_maskT[(size_t)(i0 + row) * NN + j0 + jc]) = v;
        }
        return;
    }

    // ---------------- compute_h: h = inp@W^T + b (row 0 zeroed); fp16 h + s1 + hsum partials
    int b = bidx >> 4, nb = bidx & 15;
    int lane = tid & 31, wid = tid >> 5;
    int n = nb * 256 + tid;
    for (int i = tid; i < 64 * 64; i += 256) Wsh[i] = W_w[i];
    if (tid < 64) bsh[tid] = W_b[tid];
    __syncthreads();

    float x[64];
    const float4* src = reinterpret_cast<const float4*>(inp + ((size_t)b * NN + n) * 64);
#pragma unroll
    for (int q = 0; q < 16; q++) {
        float4 v = src[q];
        x[4 * q] = v.x; x[4 * q + 1] = v.y; x[4 * q + 2] = v.z; x[4 * q + 3] = v.w;
    }
    float s1 = 0.f;
    for (int f = 0; f < 64; f++) {
        const float4* wr = reinterpret_cast<const float4*>(Wsh + f * 64);
        float t0 = bsh[f], t1 = 0.f, t2 = 0.f, t3 = 0.f;
#pragma unroll
        for (int q = 0; q < 16; q += 4) {
            float4 w0 = wr[q], w1 = wr[q + 1], w2 = wr[q + 2], w3 = wr[q + 3];
            t0 = fmaf(x[4*q+0],  w0.x, t0); t0 = fmaf(x[4*q+1],  w0.y, t0);
            t0 = fmaf(x[4*q+2],  w0.z, t0); t0 = fmaf(x[4*q+3],  w0.w, t0);
            t1 = fmaf(x[4*q+4],  w1.x, t1); t1 = fmaf(x[4*q+5],  w1.y, t1);
            t1 = fmaf(x[4*q+6],  w1.z, t1); t1 = fmaf(x[4*q+7],  w1.w, t1);
            t2 = fmaf(x[4*q+8],  w2.x, t2); t2 = fmaf(x[4*q+9],  w2.y, t2);
            t2 = fmaf(x[4*q+10], w2.z, t2); t2 = fmaf(x[4*q+11], w2.w, t2);
            t3 = fmaf(x[4*q+12], w3.x, t3); t3 = fmaf(x[4*q+13], w3.y, t3);
            t3 = fmaf(x[4*q+14], w3.z, t3); t3 = fmaf(x[4*q+15], w3.w, t3);
        }
        float acc = (t0 + t1) + (t2 + t3);
        if (n == 0) acc = 0.f;
        g_hT[((size_t)b * 64 + f) * NN + n] = __float2half(acc);
        s1 = fmaf(acc, a[(size_t)f * NN + n], s1);
        float v = acc;
#pragma unroll
        for (int off = 16; off > 0; off >>= 1)
            v += __shfl_xor_sync(0xFFFFFFFFu, v, off);
        if (lane == 0) wred[wid][f] = v;
    }
    g_s1[b * NN + n] = s1;
    __syncthreads();
    if (tid < 64) {
        float t = 0.f;
#pragma unroll
        for (int w = 0; w < 8; w++) t += wred[w][tid];
        g_hsumP[nb][b][tid] = t;
    }
}

// -------- kernel 2b: finish hsum --------
__global__ void k_hsum_final() {
    int b = threadIdx.x >> 6, f = threadIdx.x & 63;   // 512 threads
    float t = 0.f;
#pragma unroll
    for (int p = 0; p < 16; p++) t += g_hsumP[p][b][f];
    g_hsum[b * 64 + f] = t;
}

// -------- kernel 4: big GEMM (mma.sync fp16, LDSM, 3-stage 1-sync) + s2 epilogue --------
__device__ __forceinline__ void load_chunk(uint32_t stage, const char* Ah,
                                           const char* Bm, int c, int tid) {
    size_t koff = (size_t)c * 128;  // 64 fp16 = 128B per row
#pragma unroll
    for (int p = 0; p < 4; p++) {
        int q = tid + p * 256;                 // 0..1023 = 128 rows x 8 chunks
        int row = q >> 3, cb = (q & 7) * 16;
        uint32_t soff = SW128((uint32_t)(row * 128 + cb));
        size_t goff = (size_t)row * 8192 + koff + cb;
        cp16(stage + soff, Ah + goff);
        cp16(stage + 16384 + soff, Bm + goff);
    }
}

__global__ void __launch_bounds__(256, 2) k_gemm(const float* __restrict__ a) {
    extern __shared__ char smem[];
    uint32_t sb = smem_u32(smem);
    int tid = threadIdx.x, lane = tid & 31, wid = tid >> 5;
    int wm = wid & 3, wn = wid >> 2;          // warp tile: rows wm*32, cols wn*64
    int mtile = blockIdx.x, i0 = blockIdx.y * 128;
    int kslice = blockIdx.z, c0 = kslice * 16;  // 16 chunks of 64 per slice

    const char* Ah = (const char*)g_hT + (size_t)mtile * 128 * 8192;
    const char* Bm = (const char*)g_maskT + (size_t)i0 * 8192;

    float acc[2][8][4];
#pragma unroll
    for (int mt = 0; mt < 2; mt++)
#pragma unroll
        for (int nt = 0; nt < 8; nt++)
#pragma unroll
            for (int r = 0; r < 4; r++) acc[mt][nt][r] = 0.f;

    uint32_t cx = (uint32_t)((lane & 7) << 4);
    uint32_t aoff = (uint32_t)(wm * 32 + (lane & 15)) * 128u;
    uint32_t khA = (uint32_t)(((lane >> 4) & 1) << 4);
    uint32_t boff = 16384u + (uint32_t)(wn * 64 + (lane & 7) + (((lane >> 4) & 1) << 3)) * 128u;
    uint32_t khB = (uint32_t)(((lane >> 3) & 1) << 4);

    // prologue: chunks 0,1
    load_chunk(sb, Ah, Bm, c0, tid);
    CP_COMMIT();
    load_chunk(sb + STAGE_BYTES, Ah, Bm, c0 + 1, tid);
    CP_COMMIT();

    for (int c = 0; c < 16; c++) {
        asm volatile("cp.async.wait_group 1;" ::: "memory");
        __syncthreads();   // chunk c ready; all warps done computing c-1
        if (c + 2 < 16) {
            // buffer (c+2)%3 was computed at c-1; safe to overwrite now
            load_chunk(sb + (uint32_t)((c + 2) % NSTAGE) * STAGE_BYTES, Ah, Bm, c0 + c + 2, tid);
        }
        CP_COMMIT();
        uint32_t so = sb + (uint32_t)(c % NSTAGE) * STAGE_BYTES;
#pragma unroll
        for (int ks = 0; ks < 4; ks++) {
            uint32_t kA = ((uint32_t)(ks * 32) + khA) ^ cx;
            uint32_t kB = ((uint32_t)(ks * 32) + khB) ^ cx;
            uint32_t bfr[8][2];
#pragma unroll
            for (int ntp = 0; ntp < 4; ntp++)
                LDSM4(bfr[2 * ntp][0], bfr[2 * ntp][1], bfr[2 * ntp + 1][0], bfr[2 * ntp + 1][1],
                      so + boff + (uint32_t)ntp * 2048 + kB);
            uint32_t ah[2][4];
#pragma unroll
            for (int mt = 0; mt < 2; mt++)
                LDSM4(ah[mt][0], ah[mt][1], ah[mt][2], ah[mt][3],
                      so + aoff + (uint32_t)mt * 2048 + kA);
#pragma unroll
            for (int mt = 0; mt < 2; mt++)
#pragma unroll
                for (int nt = 0; nt < 8; nt++)
                    mma_f16(acc[mt][nt], ah[mt], bfr[nt]);
        }
    }

    // epilogue: s2p[kslice][b][i] = sum_f C[(b,f)][i] * a2[f][i]
    __syncthreads();
    int tig = lane & 3, grp = lane >> 2;
    float* a2s = (float*)smem;                        // [64][129]
    float* part = (float*)(smem + 64 * 129 * 4);      // [8 warps][64]
    for (int idx = tid; idx < 64 * 128; idx += 256) {
        int f = idx >> 7, cc = idx & 127;
        a2s[f * 129 + cc] = a[(size_t)(64 + f) * NN + i0 + cc];
    }
    __syncthreads();

    float p[8][2];
#pragma unroll
    for (int nt = 0; nt < 8; nt++) { p[nt][0] = 0.f; p[nt][1] = 0.f; }
#pragma unroll
    for (int mt = 0; mt < 2; mt++) {
        int f0 = (wm * 32 + mt * 16 + grp) & 63;
        int f1 = (wm * 32 + mt * 16 + grp + 8) & 63;
#pragma unroll
        for (int nt = 0; nt < 8; nt++) {
            int col = wn * 64 + nt * 8 + tig * 2;
            p[nt][0] += acc[mt][nt][0] * a2s[f0 * 129 + col] +
                        acc[mt][nt][2] * a2s[f1 * 129 + col];
            p[nt][1] += acc[mt][nt][1] * a2s[f0 * 129 + col + 1] +
                        acc[mt][nt][3] * a2s[f1 * 129 + col + 1];
        }
    }
#pragma unroll
    for (int off = 16; off >= 4; off >>= 1)
#pragma unroll
        for (int nt = 0; nt < 8; nt++) {
            p[nt][0] += __shfl_xor_sync(0xFFFFFFFFu, p[nt][0], off);
            p[nt][1] += __shfl_xor_sync(0xFFFFFFFFu, p[nt][1], off);
        }
    if (lane < 4) {
#pragma unroll
        for (int nt = 0; nt < 8; nt++) {
            part[wid * 64 + nt * 8 + tig * 2]     = p[nt][0];
            part[wid * 64 + nt * 8 + tig * 2 + 1] = p[nt][1];
        }
    }
    __syncthreads();
    {
        int bloc = tid >> 7, col = tid & 127;
        int wnn = col >> 6, c64 = col & 63;
        int w0 = wnn * 4 + bloc * 2;   // warps covering this (batch, col-block)
        float v = part[w0 * 64 + c64] + part[(w0 + 1) * 64 + c64];
        g_s2p[kslice][(size_t)(mtile * 2 + bloc) * NN + i0 + col] = v;
    }
}

// -------- kernel 5: out[b,n,f] = leaky(s[b,n] * hsum[b,f]) --------
__global__ void __launch_bounds__(256) k_out(float* __restrict__ out) {
    int b = blockIdx.y, n0 = blockIdx.x * 16, tid = threadIdx.x;
    int r = tid >> 4, q = tid & 15;
    int n = n0 + r;
    int off = b * NN + n;
    float s = 0.f;
    if (n != 0) {
        s = g_s1[off] + g_s2p[0][off] + g_s2p[1][off] + g_s2p[2][off] + g_s2p[3][off];
    }
    float4 h4 = *reinterpret_cast<const float4*>(g_hsum + b * 64 + q * 4);
    float4 v;
    v.x = s * h4.x; v.y = s * h4.y; v.z = s * h4.z; v.w = s * h4.w;
    v.x = v.x >= 0.f ? v.x : NEG_SLOPE * v.x;
    v.y = v.y >= 0.f ? v.y : NEG_SLOPE * v.y;
    v.z = v.z >= 0.f ? v.z : NEG_SLOPE * v.z;
    v.w = v.w >= 0.f ? v.w : NEG_SLOPE * v.w;
    reinterpret_cast<float4*>(out + ((size_t)b * NN + n) * 64)[q] = v;
}

extern "C" void kernel_launch(void* const* d_in, const int* in_sizes, int n_in,
                              void* d_out, int out_size) {
    const float* inp = (const float*)d_in[0];
    const int*   adj = (const int*)d_in[1];
    const float* W_w = (const float*)d_in[2];
    const float* W_b = (const float*)d_in[3];
    const float* a   = (const float*)d_in[4];
    float* out = (float*)d_out;
    cudaFuncSetAttribute(k_gemm, cudaFuncAttributeMaxDynamicSharedMemorySize, SMEM_DYN);
    k_prep<<<4224, 256>>>(inp, W_w, W_b, a, adj);
    k_hsum_final<<<1, 512>>>();
    k_gemm<<<dim3(4, 32, KSPLIT), 256, SMEM_DYN>>>(a);
    k_out<<<dim3(256, 8), 256>>>(out);
}

// round 10
// speedup vs baseline: 1.2456x; 1.0167x over previous
#include <cuda_runtime.h>
#include <cuda_fp16.h>
#include <stdint.h>

#define BB 8
#define NN 4096
#define NEG_SLOPE 0.01f
#define KSPLIT 4

// GEMM: M=512 ((b,f) rows), N=4096 (i), K=4096 (j), fp16 single pass.
// CTA tile 128x128, K chunk 64, K-split 4. B read from mask[j][i] via LDSM.trans.
#define STAGE_BYTES 32768          // A 16KB + B 16KB
#define NSTAGE 3
#define SMEM_DYN (NSTAGE * STAGE_BYTES)   // 96KB -> 2 CTAs/SM

// -------- scratch (device globals; no allocation allowed) --------
__device__ __half g_mask[(size_t)NN * NN];         // mask[j][i] = adj[j+1][i]>0 (j=4095 -> 0)
__device__ __half g_hT[(size_t)BB * 64 * NN];      // hT[b][f][n], row (b*64+f)
__device__ float g_s1[BB * NN];
__device__ float g_s2p[KSPLIT][BB * NN];           // per-K-slice partials
__device__ float g_hsumP[16][BB][64];              // per-block partials
__device__ __align__(16) float g_hsum[BB * 64];

// -------- helpers --------
__device__ __forceinline__ uint32_t smem_u32(const void* p) {
    uint32_t a;
    asm("{ .reg .u64 t; cvta.to.shared.u64 t, %1; cvt.u32.u64 %0, t; }" : "=r"(a) : "l"(p));
    return a;
}
#define SW128(x) ((x) ^ (((x) >> 3) & 0x70))
__device__ __forceinline__ void cp16(uint32_t s, const void* g) {
    asm volatile("cp.async.cg.shared.global [%0], [%1], 16;" :: "r"(s), "l"(g) : "memory");
}
#define CP_COMMIT() asm volatile("cp.async.commit_group;" ::: "memory")

__device__ __forceinline__ void mma_f16(float* c, const uint32_t* A, const uint32_t* B) {
    asm volatile(
        "mma.sync.aligned.m16n8k16.row.col.f32.f16.f16.f32 "
        "{%0,%1,%2,%3}, {%4,%5,%6,%7}, {%8,%9}, {%0,%1,%2,%3};"
        : "+f"(c[0]), "+f"(c[1]), "+f"(c[2]), "+f"(c[3])
        : "r"(A[0]), "r"(A[1]), "r"(A[2]), "r"(A[3]), "r"(B[0]), "r"(B[1]));
}
#define LDSM4(r0, r1, r2, r3, addr) \
    asm volatile("ldmatrix.sync.aligned.m8n8.x4.shared.b16 {%0,%1,%2,%3}, [%4];" \
                 : "=r"(r0), "=r"(r1), "=r"(r2), "=r"(r3) : "r"(addr))
#define LDSM4T(r0, r1, r2, r3, addr) \
    asm volatile("ldmatrix.sync.aligned.m8n8.x4.trans.shared.b16 {%0,%1,%2,%3}, [%4];" \
                 : "=r"(r0), "=r"(r1), "=r"(r2), "=r"(r3) : "r"(addr))

// -------- kernel 1 (fused): blocks 0-127 compute_h, blocks 128-4223 adj->fp16 convert --------
__global__ void __launch_bounds__(256) k_prep(const float* __restrict__ inp,
                                              const float* __restrict__ W_w,
                                              const float* __restrict__ W_b,
                                              const float* __restrict__ a,
                                              const int* __restrict__ adj) {
    int tid = threadIdx.x;
    int bidx = blockIdx.x;

    if (bidx >= 128) {
        // ---------------- streaming convert: mask[j][i] = (adj[j+1][i] > 0), j==4095 -> 0
        int j = bidx - 128;
        __half* dst = g_mask + (size_t)j * NN;
        if (j + 1 < NN) {
            const int* src = adj + (size_t)(j + 1) * NN;
#pragma unroll
            for (int p = 0; p < 4; p++) {
                int i = (tid + p * 256) * 4;
                int4 v = *reinterpret_cast<const int4*>(src + i);
                uint32_t lo = (v.x > 0 ? 0x3C00u : 0u) | (v.y > 0 ? 0x3C000000u : 0u);
                uint32_t hi = (v.z > 0 ? 0x3C00u : 0u) | (v.w > 0 ? 0x3C000000u : 0u);
                *reinterpret_cast<uint2*>(dst + i) = make_uint2(lo, hi);
            }
        } else {
#pragma unroll
            for (int p = 0; p < 4; p++) {
                int i = (tid + p * 256) * 4;
                *reinterpret_cast<uint2*>(dst + i) = make_uint2(0u, 0u);
            }
        }
        return;
    }

    // ---------------- compute_h: h = inp@W^T + b (row 0 zeroed); fp16 h + s1 + hsum partials
    __shared__ __align__(16) float Wsh[64 * 64];
    __shared__ float bsh[64];
    __shared__ float wred[8][64];
    int b = bidx >> 4, nb = bidx & 15;
    int lane = tid & 31, wid = tid >> 5;
    int n = nb * 256 + tid;
    for (int i = tid; i < 64 * 64; i += 256) Wsh[i] = W_w[i];
    if (tid < 64) bsh[tid] = W_b[tid];
    __syncthreads();

    float x[64];
    const float4* src = reinterpret_cast<const float4*>(inp + ((size_t)b * NN + n) * 64);
#pragma unroll
    for (int q = 0; q < 16; q++) {
        float4 v = src[q];
        x[4 * q] = v.x; x[4 * q + 1] = v.y; x[4 * q + 2] = v.z; x[4 * q + 3] = v.w;
    }
    float s1 = 0.f;
    for (int f = 0; f < 64; f++) {
        const float4* wr = reinterpret_cast<const float4*>(Wsh + f * 64);
        float t0 = bsh[f], t1 = 0.f, t2 = 0.f, t3 = 0.f;
#pragma unroll
        for (int q = 0; q < 16; q += 4) {
            float4 w0 = wr[q], w1 = wr[q + 1], w2 = wr[q + 2], w3 = wr[q + 3];
            t0 = fmaf(x[4*q+0],  w0.x, t0); t0 = fmaf(x[4*q+1],  w0.y, t0);
            t0 = fmaf(x[4*q+2],  w0.z, t0); t0 = fmaf(x[4*q+3],  w0.w, t0);
            t1 = fmaf(x[4*q+4],  w1.x, t1); t1 = fmaf(x[4*q+5],  w1.y, t1);
            t1 = fmaf(x[4*q+6],  w1.z, t1); t1 = fmaf(x[4*q+7],  w1.w, t1);
            t2 = fmaf(x[4*q+8],  w2.x, t2); t2 = fmaf(x[4*q+9],  w2.y, t2);
            t2 = fmaf(x[4*q+10], w2.z, t2); t2 = fmaf(x[4*q+11], w2.w, t2);
            t3 = fmaf(x[4*q+12], w3.x, t3); t3 = fmaf(x[4*q+13], w3.y, t3);
            t3 = fmaf(x[4*q+14], w3.z, t3); t3 = fmaf(x[4*q+15], w3.w, t3);
        }
        float acc = (t0 + t1) + (t2 + t3);
        if (n == 0) acc = 0.f;
        g_hT[((size_t)b * 64 + f) * NN + n] = __float2half(acc);
        s1 = fmaf(acc, a[(size_t)f * NN + n], s1);
        float v = acc;
#pragma unroll
        for (int off = 16; off > 0; off >>= 1)
            v += __shfl_xor_sync(0xFFFFFFFFu, v, off);
        if (lane == 0) wred[wid][f] = v;
    }
    g_s1[b * NN + n] = s1;
    __syncthreads();
    if (tid < 64) {
        float t = 0.f;
#pragma unroll
        for (int w = 0; w < 8; w++) t += wred[w][tid];
        g_hsumP[nb][b][tid] = t;
    }
}

// -------- kernel 2b: finish hsum --------
__global__ void k_hsum_final() {
    int b = threadIdx.x >> 6, f = threadIdx.x & 63;   // 512 threads
    float t = 0.f;
#pragma unroll
    for (int p = 0; p < 16; p++) t += g_hsumP[p][b][f];
    g_hsum[b * 64 + f] = t;
}

// -------- kernel 4: big GEMM (fp16 mma, A LDSM + B LDSM.trans, 3-stage 1-sync) --------
__device__ __forceinline__ void load_chunk(uint32_t stage, const char* Ah,
                                           const char* Bm, int c, int tid) {
    // A: 128 (b,f)-rows x 128B (64 j), SW128
    size_t koffA = (size_t)c * 128;
#pragma unroll
    for (int p = 0; p < 4; p++) {
        int q = tid + p * 256;
        int row = q >> 3, cb = (q & 7) * 16;
        cp16(stage + SW128((uint32_t)(row * 128 + cb)),
             Ah + (size_t)row * 8192 + koffA + cb);
    }
    // B: 64 j-rows x 256B (128 i), row-swizzle ^((row&15)<<4)
    size_t koffB = (size_t)c * 64 * 8192;
#pragma unroll
    for (int p = 0; p < 4; p++) {
        int q = tid + p * 256;
        int row = q >> 4, cb = (q & 15) * 16;
        uint32_t din = (uint32_t)cb ^ (uint32_t)((row & 15) << 4);
        cp16(stage + 16384u + (uint32_t)(row * 256) + din,
             Bm + koffB + (size_t)row * 8192 + cb);
    }
}

__global__ void __launch_bounds__(256, 2) k_gemm(const float* __restrict__ a) {
    extern __shared__ char smem[];
    uint32_t sb = smem_u32(smem);
    int tid = threadIdx.x, lane = tid & 31, wid = tid >> 5;
    int wm = wid & 3, wn = wid >> 2;          // warp tile: rows wm*32, cols wn*64
    int mtile = blockIdx.x, i0 = blockIdx.y * 128;
    int kslice = blockIdx.z, c0 = kslice * 16;  // 16 chunks of 64 per slice

    const char* Ah = (const char*)g_hT + (size_t)mtile * 128 * 8192;
    const char* Bm = (const char*)g_mask + (size_t)i0 * 2;

    float acc[2][8][4];
#pragma unroll
    for (int mt = 0; mt < 2; mt++)
#pragma unroll
        for (int nt = 0; nt < 8; nt++)
#pragma unroll
            for (int r = 0; r < 4; r++) acc[mt][nt][r] = 0.f;

    // A LDSM addressing (SW128)
    uint32_t cx = (uint32_t)((lane & 7) << 4);
    uint32_t aoff = (uint32_t)(wm * 32 + (lane & 15)) * 128u;
    uint32_t khA = (uint32_t)(((lane >> 4) & 1) << 4);
    // B LDSM.trans addressing (validated round 8): addr = row*256 + (col ^ ((row&15)<<4))
    uint32_t bj = (uint32_t)(lane & 15);
    uint32_t bcx = bj << 4;
    uint32_t bbase = bj * 256u + (uint32_t)(wn * 64 + ((lane >> 4) << 3)) * 2u;

    // prologue: chunks 0,1
    load_chunk(sb, Ah, Bm, c0, tid);
    CP_COMMIT();
    load_chunk(sb + STAGE_BYTES, Ah, Bm, c0 + 1, tid);
    CP_COMMIT();

    for (int c = 0; c < 16; c++) {
        asm volatile("cp.async.wait_group 1;" ::: "memory");
        __syncthreads();   // chunk c ready; all warps done computing c-1
        if (c + 2 < 16)
            load_chunk(sb + (uint32_t)((c + 2) % NSTAGE) * STAGE_BYTES, Ah, Bm, c0 + c + 2, tid);
        CP_COMMIT();
        uint32_t so = sb + (uint32_t)(c % NSTAGE) * STAGE_BYTES;
#pragma unroll
        for (int ks = 0; ks < 4; ks++) {
            uint32_t kA = ((uint32_t)(ks * 32) + khA) ^ cx;
            uint32_t bfr[8][2];
#pragma unroll
            for (int ntp = 0; ntp < 4; ntp++) {
                uint32_t boffs = (bbase + (uint32_t)(ntp * 32)) ^ bcx;
                LDSM4T(bfr[2 * ntp][0], bfr[2 * ntp][1], bfr[2 * ntp + 1][0], bfr[2 * ntp + 1][1],
                       so + 16384u + (uint32_t)(ks * 4096) + boffs);
            }
            uint32_t ah[2][4];
#pragma unroll
            for (int mt = 0; mt < 2; mt++)
                LDSM4(ah[mt][0], ah[mt][1], ah[mt][2], ah[mt][3],
                      so + aoff + (uint32_t)mt * 2048 + kA);
#pragma unroll
            for (int mt = 0; mt < 2; mt++)
#pragma unroll
                for (int nt = 0; nt < 8; nt++)
                    mma_f16(acc[mt][nt], ah[mt], bfr[nt]);
        }
    }

    // epilogue: s2p[kslice][b][i] = sum_f C[(b,f)][i] * a2[f][i]
    __syncthreads();
    int tig = lane & 3, grp = lane >> 2;
    float* a2s = (float*)smem;                        // [64][129]
    float* part = (float*)(smem + 64 * 129 * 4);      // [8 warps][64]
    for (int idx = tid; idx < 64 * 128; idx += 256) {
        int f = idx >> 7, cc = idx & 127;
        a2s[f * 129 + cc] = a[(size_t)(64 + f) * NN + i0 + cc];
    }
    __syncthreads();

    float p[8][2];
#pragma unroll
    for (int nt = 0; nt < 8; nt++) { p[nt][0] = 0.f; p[nt][1] = 0.f; }
#pragma unroll
    for (int mt = 0; mt < 2; mt++) {
        int f0 = (wm * 32 + mt * 16 + grp) & 63;
        int f1 = (wm * 32 + mt * 16 + grp + 8) & 63;
#pragma unroll
        for (int nt = 0; nt < 8; nt++) {
            int col = wn * 64 + nt * 8 + tig * 2;
            p[nt][0] += acc[mt][nt][0] * a2s[f0 * 129 + col] +
                        acc[mt][nt][2] * a2s[f1 * 129 + col];
            p[nt][1] += acc[mt][nt][1] * a2s[f0 * 129 + col + 1] +
                        acc[mt][nt][3] * a2s[f1 * 129 + col + 1];
        }
    }
#pragma unroll
    for (int off = 16; off >= 4; off >>= 1)
#pragma unroll
        for (int nt = 0; nt < 8; nt++) {
            p[nt][0] += __shfl_xor_sync(0xFFFFFFFFu, p[nt][0], off);
            p[nt][1] += __shfl_xor_sync(0xFFFFFFFFu, p[nt][1], off);
        }
    if (lane < 4) {
#pragma unroll
        for (int nt = 0; nt < 8; nt++) {
            part[wid * 64 + nt * 8 + tig * 2]     = p[nt][0];
            part[wid * 64 + nt * 8 + tig * 2 + 1] = p[nt][1];
        }
    }
    __syncthreads();
    {
        int bloc = tid >> 7, col = tid & 127;
        int wnn = col >> 6, c64 = col & 63;
        int w0 = wnn * 4 + bloc * 2;   // warps covering this (batch, col-block)
        float v = part[w0 * 64 + c64] + part[(w0 + 1) * 64 + c64];
        g_s2p[kslice][(size_t)(mtile * 2 + bloc) * NN + i0 + col] = v;
    }
}

// -------- kernel 5: out[b,n,f] = leaky(s[b,n] * hsum[b,f]) --------
__global__ void __launch_bounds__(256) k_out(float* __restrict__ out) {
    int b = blockIdx.y, n0 = blockIdx.x * 16, tid = threadIdx.x;
    int r = tid >> 4, q = tid & 15;
    int n = n0 + r;
    int off = b * NN + n;
    float s = 0.f;
    if (n != 0) {
        s = g_s1[off] + g_s2p[0][off] + g_s2p[1][off] + g_s2p[2][off] + g_s2p[3][off];
    }
    float4 h4 = *reinterpret_cast<const float4*>(g_hsum + b * 64 + q * 4);
    float4 v;
    v.x = s * h4.x; v.y = s * h4.y; v.z = s * h4.z; v.w = s * h4.w;
    v.x = v.x >= 0.f ? v.x : NEG_SLOPE * v.x;
    v.y = v.y >= 0.f ? v.y : NEG_SLOPE * v.y;
    v.z = v.z >= 0.f ? v.z : NEG_SLOPE * v.z;
    v.w = v.w >= 0.f ? v.w : NEG_SLOPE * v.w;
    reinterpret_cast<float4*>(out + ((size_t)b * NN + n) * 64)[q] = v;
}

extern "C" void kernel_launch(void* const* d_in, const int* in_sizes, int n_in,
                              void* d_out, int out_size) {
    const float* inp = (const float*)d_in[0];
    const int*   adj = (const int*)d_in[1];
    const float* W_w = (const float*)d_in[2];
    const float* W_b = (const float*)d_in[3];
    const float* a   = (const float*)d_in[4];
    float* out = (float*)d_out;
    cudaFuncSetAttribute(k_gemm, cudaFuncAttributeMaxDynamicSharedMemorySize, SMEM_DYN);
    k_prep<<<128 + 4096, 256>>>(inp, W_w, W_b, a, adj);
    k_hsum_final<<<1, 512>>>();
    k_gemm<<<dim3(4, 32, KSPLIT), 256, SMEM_DYN>>>(a);
    k_out<<<dim3(256, 8), 256>>>(out);
}